// round 16
// baseline (speedup 1.0000x reference)
#include <cuda_runtime.h>
#include <math.h>
#include <stdint.h>

// Dimensions fixed by the problem
#define ED  172          // edge_dim
#define TD  100          // time_dim
#define DQ  356          // embed(256) + time(100)
#define EMB 256          // embed_dim
#define K1P 176          // stage-1 K padded to multiple of 8
#define KT  32           // fold-GEMM k-tile depth
#define TBM 16           // batch rows per block (main kernel)
#define PA  17           // sA pitch (floats)
#define PB  260          // sB pitch (floats), float4-aligned

// ---- folded-weight scratch (device globals: no allocations allowed) ----
__device__ float g_cv[DQ];                         // bv + cos(t2v_b)@Wv_time
__device__ float g_u[DQ];                          // cv @ Wo + bo
__device__ __align__(16) float g_cpre1[EMB];       // u @ fc1 + fc1_b
__device__ __align__(16) float g_c3[EMB];          // fc2_b @ Wsum + lps_b + lpd_b
__device__ __align__(16) float g_Wsum[EMB * EMB];  // lp_src_w + lp_dst_w
__device__ __align__(16) float g_T[ED * DQ];       // Wv_e @ Wo
__device__ __align__(16) float g_W3[EMB * EMB];    // fc2_w @ Wsum
__device__ __align__(16) float g_M2[ED * EMB];     // T @ fc1
// tf32 hi/lo pre-split weights (hi = rna-tf32, lo = tf32(v - hi))
__device__ __align__(16) float g_M2hi[K1P * EMB];  // zero-padded rows 172..175
__device__ __align__(16) float g_M2lo[K1P * EMB];
__device__ __align__(16) float g_W3hi[EMB * EMB];
__device__ __align__(16) float g_W3lo[EMB * EMB];

// ---- tf32 helpers ----
__device__ __forceinline__ uint32_t tf32r(float v) {
    uint32_t u;
    asm("cvt.rna.tf32.f32 %0, %1;" : "=r"(u) : "f"(v));
    return u;
}

__device__ __forceinline__ void mma_tf32(float* c,
    uint32_t a0, uint32_t a1, uint32_t a2, uint32_t a3,
    uint32_t b0, uint32_t b1)
{
    asm volatile(
        "mma.sync.aligned.m16n8k8.row.col.f32.tf32.tf32.f32 "
        "{%0,%1,%2,%3}, {%4,%5,%6,%7}, {%8,%9}, {%0,%1,%2,%3};"
        : "+f"(c[0]), "+f"(c[1]), "+f"(c[2]), "+f"(c[3])
        : "r"(a0), "r"(a1), "r"(a2), "r"(a3), "r"(b0), "r"(b1));
}

// ============================================================
// Tiled fold GEMM (unchanged, proven)
// ============================================================
__device__ __forceinline__ void fold_gemm_tile(
    const float* __restrict__ A, int lda, int M,
    const float* __restrict__ B, int ldb, int K, int N,
    float* __restrict__ C, int ldc,
    int tileM, int tileN, float* As /*[KT*36]*/, float* Bs /*[KT*33]*/)
{
    const int tid = threadIdx.x;
    const int m0  = (tid & 7) * 4;
    const int n   = tid >> 3;
    const int nk  = (K + KT - 1) / KT;
    float acc[4] = {0.f, 0.f, 0.f, 0.f};
    float ra[4], rb[4];

    #pragma unroll
    for (int p = 0; p < 4; p++) {
        int idx = tid + 256 * p;
        int gm = tileM + (idx >> 5), gk = idx & 31;
        ra[p] = (gm < M && gk < K) ? A[gm * lda + gk] : 0.f;
        int gk2 = idx >> 5, gn = tileN + (idx & 31);
        rb[p] = (gk2 < K && gn < N) ? B[gk2 * ldb + gn] : 0.f;
    }

    for (int kt = 0; kt < nk; kt++) {
        __syncthreads();
        #pragma unroll
        for (int p = 0; p < 4; p++) {
            int idx = tid + 256 * p;
            As[(idx & 31) * 36 + (idx >> 5)] = ra[p];
            Bs[(idx >> 5) * 33 + (idx & 31)] = rb[p];
        }
        __syncthreads();
        if (kt + 1 < nk) {
            int k0n = (kt + 1) * KT;
            #pragma unroll
            for (int p = 0; p < 4; p++) {
                int idx = tid + 256 * p;
                int gm = tileM + (idx >> 5), gk = k0n + (idx & 31);
                ra[p] = (gm < M && gk < K) ? A[gm * lda + gk] : 0.f;
                int gk2 = k0n + (idx >> 5), gn = tileN + (idx & 31);
                rb[p] = (gk2 < K && gn < N) ? B[gk2 * ldb + gn] : 0.f;
            }
        }
        #pragma unroll
        for (int kk = 0; kk < KT; kk++) {
            float4 a = *(const float4*)(As + kk * 36 + m0);
            float  b = Bs[kk * 33 + n];
            acc[0] = fmaf(a.x, b, acc[0]);
            acc[1] = fmaf(a.y, b, acc[1]);
            acc[2] = fmaf(a.z, b, acc[2]);
            acc[3] = fmaf(a.w, b, acc[3]);
        }
    }
    int gn = tileN + n;
    if (gn < N) {
        #pragma unroll
        for (int i = 0; i < 4; i++) {
            int gm = tileM + m0 + i;
            if (gm < M) C[gm * ldc + gn] = acc[i];
        }
    }
}

// ============================================================
// Parallel GEMV for constant-vector folds (8 k-slices x 32 cols)
// ============================================================
__device__ __forceinline__ void fold_gemv32(
    const float* __restrict__ xs, const float* __restrict__ W, int ldw, int K,
    const float* __restrict__ bias1, const float* __restrict__ bias2,
    float* __restrict__ y, int N, int j0, float* part /*[8*33]*/)
{
    const int tid = threadIdx.x;
    const int jl = tid & 31, slice = tid >> 5;
    const int j = j0 + jl;
    const int chunk = (K + 7) >> 3;
    const int k0 = slice * chunk;
    const int k1 = (k0 + chunk < K) ? (k0 + chunk) : K;
    float s = 0.f;
    if (j < N) {
        #pragma unroll 8
        for (int k = k0; k < k1; k++)
            s = fmaf(xs[k], W[k * ldw + j], s);
    }
    part[slice * 33 + jl] = s;
    __syncthreads();
    if (slice == 0 && j < N) {
        float t = bias1[j];
        if (bias2) t += bias2[j];
        #pragma unroll
        for (int p = 0; p < 8; p++) t += part[p * 33 + jl];
        y[j] = t;
    }
}

// ============================================================
// P1: T = Wv_e @ Wo (72) ; Wsum (16) ; cv GEMV (12)
// ============================================================
#define P1_T   72
#define P1_WS  16
#define P1_CV  12
#define P1_GRID (P1_T + P1_WS + P1_CV)

__global__ void __launch_bounds__(256) tgat_preP1(
    const float* __restrict__ Wv,    const float* __restrict__ bv,
    const float* __restrict__ t2v_b, const float* __restrict__ Wo,
    const float* __restrict__ lps_w, const float* __restrict__ lpd_w)
{
    __shared__ __align__(16) float As[KT * 36];
    __shared__ float Bs[KT * 33];
    __shared__ float xs[TD];
    __shared__ float part[8 * 33];

    const int bid = blockIdx.x;
    const int tid = threadIdx.x;

    if (bid < P1_T) {
        const int NT = 12;
        int tm = (bid / NT) * 32, tn = (bid % NT) * 32;
        fold_gemm_tile(Wv + EMB * DQ, DQ, ED,
                       Wo, DQ, DQ, DQ,
                       g_T, DQ, tm, tn, As, Bs);
    } else if (bid < P1_T + P1_WS) {
        const float4* a4 = (const float4*)lps_w;
        const float4* b4 = (const float4*)lpd_w;
        float4* s4 = (float4*)g_Wsum;
        int nq = (EMB * EMB) / 4;
        for (int i = (bid - P1_T) * 256 + tid; i < nq; i += P1_WS * 256) {
            float4 a = a4[i], b = b4[i];
            s4[i] = make_float4(a.x + b.x, a.y + b.y, a.z + b.z, a.w + b.w);
        }
    } else {
        if (tid < TD) xs[tid] = cosf(t2v_b[tid]);
        __syncthreads();
        int j0 = (bid - P1_T - P1_WS) * 32;
        fold_gemv32(xs, Wv + (EMB + ED) * DQ, DQ, TD, bv, 0, g_cv, DQ, j0, part);
    }
}

// ============================================================
// P2: M2 = T @ fc1 (48) ; W3 = fc2 @ Wsum (64) ; u GEMV (12) ; c3 GEMV (8)
// ============================================================
#define P2_M2  48
#define P2_W3  64
#define P2_U   12
#define P2_C3  8
#define P2_GRID (P2_M2 + P2_W3 + P2_U + P2_C3)

__global__ void __launch_bounds__(256) tgat_preP2(
    const float* __restrict__ fc1_w, const float* __restrict__ fc2_w,
    const float* __restrict__ fc2_b, const float* __restrict__ Wo,
    const float* __restrict__ bo,
    const float* __restrict__ lps_b, const float* __restrict__ lpd_b)
{
    __shared__ __align__(16) float As[KT * 36];
    __shared__ float Bs[KT * 33];
    __shared__ float xs[DQ];
    __shared__ float part[8 * 33];

    const int bid = blockIdx.x;
    const int tid = threadIdx.x;

    if (bid < P2_M2) {
        const int NT = 8;
        int tm = (bid / NT) * 32, tn = (bid % NT) * 32;
        fold_gemm_tile(g_T, DQ, ED,
                       fc1_w, EMB, DQ, EMB,
                       g_M2, EMB, tm, tn, As, Bs);
    } else if (bid < P2_M2 + P2_W3) {
        const int NT = 8;
        int b2 = bid - P2_M2;
        int tm = (b2 / NT) * 32, tn = (b2 % NT) * 32;
        fold_gemm_tile(fc2_w, EMB, EMB,
                       g_Wsum, EMB, EMB, EMB,
                       g_W3, EMB, tm, tn, As, Bs);
    } else if (bid < P2_M2 + P2_W3 + P2_U) {
        for (int k = tid; k < DQ; k += 256) xs[k] = g_cv[k];
        __syncthreads();
        int j0 = (bid - P2_M2 - P2_W3) * 32;
        fold_gemv32(xs, Wo, DQ, DQ, bo, 0, g_u, DQ, j0, part);
    } else {
        for (int k = tid; k < EMB; k += 256) xs[k] = fc2_b[k];
        __syncthreads();
        int j0 = (bid - P2_M2 - P2_W3 - P2_U) * 32;
        fold_gemv32(xs, g_Wsum, EMB, EMB, lps_b, lpd_b, g_c3, EMB, j0, part);
    }
}

// ============================================================
// P3: cpre1 (8 blocks) ; tf32 hi/lo split of g_M2 and g_W3 (432 blocks)
// ============================================================
#define SPLIT_M2 (K1P * EMB)                       // 45056
#define SPLIT_W3 (EMB * EMB)                       // 65536
#define P3_CP   8
#define P3_SPL  ((SPLIT_M2 + SPLIT_W3) / 256)      // 432
#define P3_GRID (P3_CP + P3_SPL)

__global__ void __launch_bounds__(256) tgat_preP3(
    const float* __restrict__ fc1_w, const float* __restrict__ fc1_b)
{
    __shared__ float xs[DQ];
    __shared__ float part[8 * 33];
    const int bid = blockIdx.x;
    const int tid = threadIdx.x;

    if (bid < P3_CP) {
        for (int k = tid; k < DQ; k += 256) xs[k] = g_u[k];
        __syncthreads();
        fold_gemv32(xs, fc1_w, EMB, DQ, fc1_b, 0, g_cpre1, EMB, bid * 32, part);
    } else {
        int idx = (bid - P3_CP) * 256 + tid;
        float v;
        float *dhi, *dlo;
        int di;
        if (idx < SPLIT_M2) {
            int e = idx >> 8;
            v = (e < ED) ? g_M2[e * EMB + (idx & 255)] : 0.f;   // zero-pad rows 172..175
            dhi = g_M2hi; dlo = g_M2lo; di = idx;
        } else {
            di = idx - SPLIT_M2;
            v = g_W3[di];
            dhi = g_W3hi; dlo = g_W3lo;
        }
        uint32_t hu = tf32r(v);
        float hf = __uint_as_float(hu);
        uint32_t lu = tf32r(v - hf);
        dhi[di] = hf;
        dlo[di] = __uint_as_float(lu);
    }
}

// ============================================================
// mma GEMM stage: acc[t][0..3] += A[16 x 8*NC] @ B[8*NC x 256],
// 3xTF32 with PRE-SPLIT B (hi/lo from gmem, zero ALU per B value).
// Staging: register prefetch (load chunk c+1 while computing c).
// 8 warps; warp owns n-slice [32w, 32w+32) = 4 n-tiles.
// ============================================================
template <int NC>
__device__ __forceinline__ void mma_gemm_stage(
    const float4* __restrict__ gBhi, const float4* __restrict__ gBlo,
    const float* __restrict__ sA, float* __restrict__ sBhi, float* __restrict__ sBlo,
    float acc[4][4], int lane, int warp, int tid)
{
    const int s = lane & 3, q = lane >> 2;
    const int n0 = warp * 32 + q;
    // staging indices: thread covers 2 float4 (i4 = tid, tid+256) of 512 per chunk
    const int kkA = tid >> 6,         n4A = tid & 63;
    const int kkB = (tid + 256) >> 6, n4B = (tid + 256) & 63;

    // prefetch chunk 0
    float4 rh0 = gBhi[kkA * 64 + n4A], rh1 = gBhi[kkB * 64 + n4B];
    float4 rl0 = gBlo[kkA * 64 + n4A], rl1 = gBlo[kkB * 64 + n4B];

    #pragma unroll 1
    for (int c = 0; c < NC; c++) {
        __syncthreads();                          // previous chunk's reads done
        *(float4*)(sBhi + kkA * PB + n4A * 4) = rh0;
        *(float4*)(sBhi + kkB * PB + n4B * 4) = rh1;
        *(float4*)(sBlo + kkA * PB + n4A * 4) = rl0;
        *(float4*)(sBlo + kkB * PB + n4B * 4) = rl1;
        __syncthreads();
        if (c + 1 < NC) {                         // LDG for c+1 overlaps compute
            int base = (c + 1) * 8 * 64;
            rh0 = gBhi[base + kkA * 64 + n4A];
            rh1 = gBhi[base + kkB * 64 + n4B];
            rl0 = gBlo[base + kkA * 64 + n4A];
            rl1 = gBlo[base + kkB * 64 + n4B];
        }

        // A fragment (m16n8k8 tf32 row layout), split inline (cheap)
        const float* Ap = sA + (c * 8 + s) * PA + q;
        float af0 = Ap[0];           // (row q,   k = 8c+s)
        float af1 = Ap[8];           // (row q+8, k = 8c+s)
        float af2 = Ap[4 * PA];      // (row q,   k = 8c+s+4)
        float af3 = Ap[4 * PA + 8];  // (row q+8, k = 8c+s+4)
        uint32_t ah0 = tf32r(af0), ah1 = tf32r(af1),
                 ah2 = tf32r(af2), ah3 = tf32r(af3);
        uint32_t al0 = tf32r(af0 - __uint_as_float(ah0));
        uint32_t al1 = tf32r(af1 - __uint_as_float(ah1));
        uint32_t al2 = tf32r(af2 - __uint_as_float(ah2));
        uint32_t al3 = tf32r(af3 - __uint_as_float(ah3));

        #pragma unroll
        for (int t = 0; t < 4; t++) {
            int n = n0 + t * 8;
            uint32_t b0h = __float_as_uint(sBhi[s * PB + n]);
            uint32_t b1h = __float_as_uint(sBhi[(s + 4) * PB + n]);
            uint32_t b0l = __float_as_uint(sBlo[s * PB + n]);
            uint32_t b1l = __float_as_uint(sBlo[(s + 4) * PB + n]);
            mma_tf32(acc[t], ah0, ah1, ah2, ah3, b0h, b1h);
            mma_tf32(acc[t], ah0, ah1, ah2, ah3, b0l, b1l);
            mma_tf32(acc[t], al0, al1, al2, al3, b0h, b1h);
        }
    }
    __syncthreads();
}

// ============================================================
// Main fused kernel (tensor-core): 256 threads (8 warps), TBM=16.
//   stage1: h  = relu(edge @ M2 + cpre1)   [mma 3xTF32]
//   stage2: hp = relu(h @ W3 + c3)         [mma 3xTF32]
//   stage3: prob = sigmoid(hp . lpo_w + lpo_b)
// ============================================================
__global__ void __launch_bounds__(256) tgat_main(
    const float* __restrict__ edge,
    const float* __restrict__ lpo_w, const float* __restrict__ lpo_b,
    float* __restrict__ out, int B, int dup)
{
    __shared__ __align__(16) float sA[EMB * PA];    // [k][m] pitch 17, 17.4 KB
    __shared__ __align__(16) float sBhi[8 * PB];    // 8.3 KB
    __shared__ __align__(16) float sBlo[8 * PB];    // 8.3 KB
    __shared__ float red[8 * TBM];

    const int tid  = threadIdx.x;
    const int lane = tid & 31;
    const int warp = tid >> 5;
    const int s    = lane & 3;
    const int q    = lane >> 2;
    const int b0   = blockIdx.x * TBM;

    // load edge [16][172] -> sA col-major [e][r]; zero-pad rows 172..175
    for (int i = tid; i < TBM * ED; i += 256) {
        int r = i / ED, e = i - r * ED;
        float v = (b0 + r < B) ? edge[b0 * ED + i] : 0.f;
        sA[e * PA + r] = v;
    }
    if (tid < 64) sA[(ED + (tid >> 4)) * PA + (tid & 15)] = 0.f;
    __syncthreads();

    float acc[4][4];
    #pragma unroll
    for (int t = 0; t < 4; t++)
        acc[t][0] = acc[t][1] = acc[t][2] = acc[t][3] = 0.f;

    // ---- stage 1: edge @ M2 (K = 176 padded, 22 chunks) ----
    mma_gemm_stage<K1P / 8>((const float4*)g_M2hi, (const float4*)g_M2lo,
                            sA, sBhi, sBlo, acc, lane, warp, tid);

    // ---- epilogue 1: h = relu(acc + cpre1) -> sA [col][row] ----
    #pragma unroll
    for (int t = 0; t < 4; t++) {
        int col0 = warp * 32 + t * 8 + s * 2;
        float cp0 = g_cpre1[col0], cp1 = g_cpre1[col0 + 1];
        sA[col0 * PA + q]           = fmaxf(acc[t][0] + cp0, 0.f);
        sA[(col0 + 1) * PA + q]     = fmaxf(acc[t][1] + cp1, 0.f);
        sA[col0 * PA + q + 8]       = fmaxf(acc[t][2] + cp0, 0.f);
        sA[(col0 + 1) * PA + q + 8] = fmaxf(acc[t][3] + cp1, 0.f);
        acc[t][0] = acc[t][1] = acc[t][2] = acc[t][3] = 0.f;
    }
    __syncthreads();

    // ---- stage 2: h @ W3 (K = 256, 32 chunks) ----
    mma_gemm_stage<EMB / 8>((const float4*)g_W3hi, (const float4*)g_W3lo,
                            sA, sBhi, sBlo, acc, lane, warp, tid);

    // ---- epilogue 2: hp = relu(acc + c3); row-dots with lpo_w ----
    float rs0 = 0.f, rs1 = 0.f;
    #pragma unroll
    for (int t = 0; t < 4; t++) {
        int col0 = warp * 32 + t * 8 + s * 2;
        float c30 = g_c3[col0], c31 = g_c3[col0 + 1];
        float w0 = lpo_w[col0], w1 = lpo_w[col0 + 1];
        rs0 += fmaxf(acc[t][0] + c30, 0.f) * w0 + fmaxf(acc[t][1] + c31, 0.f) * w1;
        rs1 += fmaxf(acc[t][2] + c30, 0.f) * w0 + fmaxf(acc[t][3] + c31, 0.f) * w1;
    }
    rs0 += __shfl_xor_sync(0xffffffffu, rs0, 1);
    rs0 += __shfl_xor_sync(0xffffffffu, rs0, 2);
    rs1 += __shfl_xor_sync(0xffffffffu, rs1, 1);
    rs1 += __shfl_xor_sync(0xffffffffu, rs1, 2);
    if (s == 0) {
        red[warp * TBM + q]     = rs0;   // row q
        red[warp * TBM + 8 + q] = rs1;   // row q+8
    }
    __syncthreads();

    if (tid < TBM) {
        float sv = lpo_b[0];
        #pragma unroll
        for (int w2 = 0; w2 < 8; w2++) sv += red[w2 * TBM + tid];
        float prob = 1.f / (1.f + expf(-sv));
        int b = b0 + tid;
        if (b < B) {
            out[b] = prob;
            if (dup) out[B + b] = prob;
        }
    }
}

// ============================================================
// Launch. Input order (metadata):
//  0 src 1 dst 2 time 3 edge_feats 4 t2v_w 5 t2v_b
//  6 Wq 7 bq 8 Wk 9 bk 10 Wv 11 bv 12 Wo 13 bo
//  14 fc1_w 15 fc1_b 16 fc2_w 17 fc2_b
//  18 lp_src_w 19 lp_src_b 20 lp_dst_w 21 lp_dst_b 22 lp_out_w 23 lp_out_b
// ============================================================
extern "C" void kernel_launch(void* const* d_in, const int* in_sizes, int n_in,
                              void* d_out, int out_size)
{
    const float* edge  = (const float*)d_in[3];
    const float* t2v_b = (const float*)d_in[5];
    const float* Wv    = (const float*)d_in[10];
    const float* bv    = (const float*)d_in[11];
    const float* Wo    = (const float*)d_in[12];
    const float* bo    = (const float*)d_in[13];
    const float* fc1_w = (const float*)d_in[14];
    const float* fc1_b = (const float*)d_in[15];
    const float* fc2_w = (const float*)d_in[16];
    const float* fc2_b = (const float*)d_in[17];
    const float* lps_w = (const float*)d_in[18];
    const float* lps_b = (const float*)d_in[19];
    const float* lpd_w = (const float*)d_in[20];
    const float* lpd_b = (const float*)d_in[21];
    const float* lpo_w = (const float*)d_in[22];
    const float* lpo_b = (const float*)d_in[23];

    const int B = in_sizes[0];
    float* out = (float*)d_out;
    const int dup = (out_size >= 2 * B) ? 1 : 0;

    tgat_preP1<<<P1_GRID, 256>>>(Wv, bv, t2v_b, Wo, lps_w, lpd_w);
    tgat_preP2<<<P2_GRID, 256>>>(fc1_w, fc2_w, fc2_b, Wo, bo, lps_b, lpd_b);
    tgat_preP3<<<P3_GRID, 256>>>(fc1_w, fc1_b);
    tgat_main<<<(B + TBM - 1) / TBM, 256>>>(edge, lpo_w, lpo_b, out, B, dup);
}

// round 17
// speedup vs baseline: 1.3804x; 1.3804x over previous
#include <cuda_runtime.h>
#include <math.h>
#include <stdint.h>

// Dimensions fixed by the problem
#define ED  172          // edge_dim
#define TD  100          // time_dim
#define DQ  356          // embed(256) + time(100)
#define EMB 256          // embed_dim
#define K1P 176          // stage-1 K padded to multiple of 8
#define KT  32           // fold-GEMM k-tile depth
#define TBM 32           // batch rows per block (main kernel, 2 m16 tiles)
#define PA  36           // sA pitch (floats): A-frag loads ~conflict-free
#define PB  264          // sB pitch (floats): 8s+q distinct banks

// ---- folded-weight scratch (device globals: no allocations allowed) ----
__device__ float g_cv[DQ];                         // bv + cos(t2v_b)@Wv_time
__device__ float g_u[DQ];                          // cv @ Wo + bo
__device__ __align__(16) float g_cpre1[EMB];       // u @ fc1 + fc1_b
__device__ __align__(16) float g_c3[EMB];          // fc2_b @ Wsum + lps_b + lpd_b
__device__ __align__(16) float g_Wsum[EMB * EMB];  // lp_src_w + lp_dst_w
__device__ __align__(16) float g_T[ED * DQ];       // Wv_e @ Wo
__device__ __align__(16) float g_W3[EMB * EMB];    // fc2_w @ Wsum
__device__ __align__(16) float g_M2[ED * EMB];     // T @ fc1

// ---- tf32 helpers ----
__device__ __forceinline__ uint32_t tf32r(float v) {
    uint32_t u;
    asm("cvt.rna.tf32.f32 %0, %1;" : "=r"(u) : "f"(v));
    return u;
}

__device__ __forceinline__ void mma_tf32(float* c,
    uint32_t a0, uint32_t a1, uint32_t a2, uint32_t a3,
    uint32_t b0, uint32_t b1)
{
    asm volatile(
        "mma.sync.aligned.m16n8k8.row.col.f32.tf32.tf32.f32 "
        "{%0,%1,%2,%3}, {%4,%5,%6,%7}, {%8,%9}, {%0,%1,%2,%3};"
        : "+f"(c[0]), "+f"(c[1]), "+f"(c[2]), "+f"(c[3])
        : "r"(a0), "r"(a1), "r"(a2), "r"(a3), "r"(b0), "r"(b1));
}

// ============================================================
// Tiled fold GEMM (unchanged, proven)
// ============================================================
__device__ __forceinline__ void fold_gemm_tile(
    const float* __restrict__ A, int lda, int M,
    const float* __restrict__ B, int ldb, int K, int N,
    float* __restrict__ C, int ldc,
    int tileM, int tileN, float* As /*[KT*36]*/, float* Bs /*[KT*33]*/)
{
    const int tid = threadIdx.x;
    const int m0  = (tid & 7) * 4;
    const int n   = tid >> 3;
    const int nk  = (K + KT - 1) / KT;
    float acc[4] = {0.f, 0.f, 0.f, 0.f};
    float ra[4], rb[4];

    #pragma unroll
    for (int p = 0; p < 4; p++) {
        int idx = tid + 256 * p;
        int gm = tileM + (idx >> 5), gk = idx & 31;
        ra[p] = (gm < M && gk < K) ? A[gm * lda + gk] : 0.f;
        int gk2 = idx >> 5, gn = tileN + (idx & 31);
        rb[p] = (gk2 < K && gn < N) ? B[gk2 * ldb + gn] : 0.f;
    }

    for (int kt = 0; kt < nk; kt++) {
        __syncthreads();
        #pragma unroll
        for (int p = 0; p < 4; p++) {
            int idx = tid + 256 * p;
            As[(idx & 31) * 36 + (idx >> 5)] = ra[p];
            Bs[(idx >> 5) * 33 + (idx & 31)] = rb[p];
        }
        __syncthreads();
        if (kt + 1 < nk) {
            int k0n = (kt + 1) * KT;
            #pragma unroll
            for (int p = 0; p < 4; p++) {
                int idx = tid + 256 * p;
                int gm = tileM + (idx >> 5), gk = k0n + (idx & 31);
                ra[p] = (gm < M && gk < K) ? A[gm * lda + gk] : 0.f;
                int gk2 = k0n + (idx >> 5), gn = tileN + (idx & 31);
                rb[p] = (gk2 < K && gn < N) ? B[gk2 * ldb + gn] : 0.f;
            }
        }
        #pragma unroll
        for (int kk = 0; kk < KT; kk++) {
            float4 a = *(const float4*)(As + kk * 36 + m0);
            float  b = Bs[kk * 33 + n];
            acc[0] = fmaf(a.x, b, acc[0]);
            acc[1] = fmaf(a.y, b, acc[1]);
            acc[2] = fmaf(a.z, b, acc[2]);
            acc[3] = fmaf(a.w, b, acc[3]);
        }
    }
    int gn = tileN + n;
    if (gn < N) {
        #pragma unroll
        for (int i = 0; i < 4; i++) {
            int gm = tileM + m0 + i;
            if (gm < M) C[gm * ldc + gn] = acc[i];
        }
    }
}

// ============================================================
// Parallel GEMV for constant-vector folds (8 k-slices x 32 cols)
// ============================================================
__device__ __forceinline__ void fold_gemv32(
    const float* __restrict__ xs, const float* __restrict__ W, int ldw, int K,
    const float* __restrict__ bias1, const float* __restrict__ bias2,
    float* __restrict__ y, int N, int j0, float* part /*[8*33]*/)
{
    const int tid = threadIdx.x;
    const int jl = tid & 31, slice = tid >> 5;
    const int j = j0 + jl;
    const int chunk = (K + 7) >> 3;
    const int k0 = slice * chunk;
    const int k1 = (k0 + chunk < K) ? (k0 + chunk) : K;
    float s = 0.f;
    if (j < N) {
        #pragma unroll 8
        for (int k = k0; k < k1; k++)
            s = fmaf(xs[k], W[k * ldw + j], s);
    }
    part[slice * 33 + jl] = s;
    __syncthreads();
    if (slice == 0 && j < N) {
        float t = bias1[j];
        if (bias2) t += bias2[j];
        #pragma unroll
        for (int p = 0; p < 8; p++) t += part[p * 33 + jl];
        y[j] = t;
    }
}

// ============================================================
// P1: T = Wv_e @ Wo (72) ; Wsum (16) ; cv GEMV (12)
// ============================================================
#define P1_T   72
#define P1_WS  16
#define P1_CV  12
#define P1_GRID (P1_T + P1_WS + P1_CV)

__global__ void __launch_bounds__(256) tgat_preP1(
    const float* __restrict__ Wv,    const float* __restrict__ bv,
    const float* __restrict__ t2v_b, const float* __restrict__ Wo,
    const float* __restrict__ lps_w, const float* __restrict__ lpd_w)
{
    __shared__ __align__(16) float As[KT * 36];
    __shared__ float Bs[KT * 33];
    __shared__ float xs[TD];
    __shared__ float part[8 * 33];

    const int bid = blockIdx.x;
    const int tid = threadIdx.x;

    if (bid < P1_T) {
        const int NT = 12;
        int tm = (bid / NT) * 32, tn = (bid % NT) * 32;
        fold_gemm_tile(Wv + EMB * DQ, DQ, ED,
                       Wo, DQ, DQ, DQ,
                       g_T, DQ, tm, tn, As, Bs);
    } else if (bid < P1_T + P1_WS) {
        const float4* a4 = (const float4*)lps_w;
        const float4* b4 = (const float4*)lpd_w;
        float4* s4 = (float4*)g_Wsum;
        int nq = (EMB * EMB) / 4;
        for (int i = (bid - P1_T) * 256 + tid; i < nq; i += P1_WS * 256) {
            float4 a = a4[i], b = b4[i];
            s4[i] = make_float4(a.x + b.x, a.y + b.y, a.z + b.z, a.w + b.w);
        }
    } else {
        if (tid < TD) xs[tid] = cosf(t2v_b[tid]);
        __syncthreads();
        int j0 = (bid - P1_T - P1_WS) * 32;
        fold_gemv32(xs, Wv + (EMB + ED) * DQ, DQ, TD, bv, 0, g_cv, DQ, j0, part);
    }
}

// ============================================================
// P2: M2 = T @ fc1 (48) ; W3 = fc2 @ Wsum (64) ; u GEMV (12) ; c3 GEMV (8)
// ============================================================
#define P2_M2  48
#define P2_W3  64
#define P2_U   12
#define P2_C3  8
#define P2_GRID (P2_M2 + P2_W3 + P2_U + P2_C3)

__global__ void __launch_bounds__(256) tgat_preP2(
    const float* __restrict__ fc1_w, const float* __restrict__ fc2_w,
    const float* __restrict__ fc2_b, const float* __restrict__ Wo,
    const float* __restrict__ bo,
    const float* __restrict__ lps_b, const float* __restrict__ lpd_b)
{
    __shared__ __align__(16) float As[KT * 36];
    __shared__ float Bs[KT * 33];
    __shared__ float xs[DQ];
    __shared__ float part[8 * 33];

    const int bid = blockIdx.x;
    const int tid = threadIdx.x;

    if (bid < P2_M2) {
        const int NT = 8;
        int tm = (bid / NT) * 32, tn = (bid % NT) * 32;
        fold_gemm_tile(g_T, DQ, ED,
                       fc1_w, EMB, DQ, EMB,
                       g_M2, EMB, tm, tn, As, Bs);
    } else if (bid < P2_M2 + P2_W3) {
        const int NT = 8;
        int b2 = bid - P2_M2;
        int tm = (b2 / NT) * 32, tn = (b2 % NT) * 32;
        fold_gemm_tile(fc2_w, EMB, EMB,
                       g_Wsum, EMB, EMB, EMB,
                       g_W3, EMB, tm, tn, As, Bs);
    } else if (bid < P2_M2 + P2_W3 + P2_U) {
        for (int k = tid; k < DQ; k += 256) xs[k] = g_cv[k];
        __syncthreads();
        int j0 = (bid - P2_M2 - P2_W3) * 32;
        fold_gemv32(xs, Wo, DQ, DQ, bo, 0, g_u, DQ, j0, part);
    } else {
        for (int k = tid; k < EMB; k += 256) xs[k] = fc2_b[k];
        __syncthreads();
        int j0 = (bid - P2_M2 - P2_W3 - P2_U) * 32;
        fold_gemv32(xs, g_Wsum, EMB, EMB, lps_b, lpd_b, g_c3, EMB, j0, part);
    }
}

// ============================================================
// P3: cpre1 = u @ fc1 + fc1_b  (8 blocks)
// ============================================================
__global__ void __launch_bounds__(256) tgat_preP3(
    const float* __restrict__ fc1_w, const float* __restrict__ fc1_b)
{
    __shared__ float xs[DQ];
    __shared__ float part[8 * 33];
    const int tid = threadIdx.x;
    for (int k = tid; k < DQ; k += 256) xs[k] = g_u[k];
    __syncthreads();
    fold_gemv32(xs, fc1_w, EMB, DQ, fc1_b, 0, g_cpre1, EMB, blockIdx.x * 32, part);
}

// ============================================================
// mma GEMM stage (TBM=32): acc[mt][t][0..3] += A[32 x 8*NC] @ B[8*NC x 256]
// 3xTF32; B staged fp32 (single stream) with register prefetch, split at use
// (amortized over both m-tiles). 8 warps; warp owns n-slice [32w, 32w+32).
// ============================================================
template <int NC>
__device__ __forceinline__ void mma_gemm_stage(
    const float4* __restrict__ gB, int Krows,
    const float* __restrict__ sA, float* __restrict__ sB,
    float acc[2][4][4], int lane, int warp, int tid)
{
    const int s = lane & 3, q = lane >> 2;
    const int n0 = warp * 32 + q;
    // staging: 8 rows x 64 float4 = 512 float4 per chunk; 2 per thread
    const int kkA = tid >> 6,         n4A = tid & 63;
    const int kkB = (tid + 256) >> 6, n4B = (tid + 256) & 63;

    float4 r0 = (kkA < Krows) ? gB[kkA * 64 + n4A] : make_float4(0.f, 0.f, 0.f, 0.f);
    float4 r1 = (kkB < Krows) ? gB[kkB * 64 + n4B] : make_float4(0.f, 0.f, 0.f, 0.f);

    #pragma unroll 1
    for (int c = 0; c < NC; c++) {
        __syncthreads();                          // previous chunk's reads done
        *(float4*)(sB + kkA * PB + n4A * 4) = r0;
        *(float4*)(sB + kkB * PB + n4B * 4) = r1;
        __syncthreads();
        if (c + 1 < NC) {                         // LDG for c+1 overlaps compute
            int k0n = (c + 1) * 8;
            int gkA = k0n + kkA, gkB = k0n + kkB;
            r0 = (gkA < Krows) ? gB[gkA * 64 + n4A] : make_float4(0.f, 0.f, 0.f, 0.f);
            r1 = (gkB < Krows) ? gB[gkB * 64 + n4B] : make_float4(0.f, 0.f, 0.f, 0.f);
        }

        // A fragments (m16n8k8 tf32 row layout) for both m-tiles, split inline
        const float* Ap = sA + (c * 8 + s) * PA + q;
        uint32_t ah[2][4], al[2][4];
        #pragma unroll
        for (int mt = 0; mt < 2; mt++) {
            int mo = mt * 16;
            float f0 = Ap[mo];               // (row mo+q,   k = 8c+s)
            float f1 = Ap[mo + 8];           // (row mo+q+8, k = 8c+s)
            float f2 = Ap[4 * PA + mo];      // (row mo+q,   k = 8c+s+4)
            float f3 = Ap[4 * PA + mo + 8];  // (row mo+q+8, k = 8c+s+4)
            ah[mt][0] = tf32r(f0); ah[mt][1] = tf32r(f1);
            ah[mt][2] = tf32r(f2); ah[mt][3] = tf32r(f3);
            al[mt][0] = tf32r(f0 - __uint_as_float(ah[mt][0]));
            al[mt][1] = tf32r(f1 - __uint_as_float(ah[mt][1]));
            al[mt][2] = tf32r(f2 - __uint_as_float(ah[mt][2]));
            al[mt][3] = tf32r(f3 - __uint_as_float(ah[mt][3]));
        }

        #pragma unroll
        for (int t = 0; t < 4; t++) {
            int n = n0 + t * 8;
            float b0f = sB[s * PB + n];
            float b1f = sB[(s + 4) * PB + n];
            uint32_t b0h = tf32r(b0f), b1h = tf32r(b1f);
            uint32_t b0l = tf32r(b0f - __uint_as_float(b0h));
            uint32_t b1l = tf32r(b1f - __uint_as_float(b1h));
            #pragma unroll
            for (int mt = 0; mt < 2; mt++) {
                mma_tf32(acc[mt][t], ah[mt][0], ah[mt][1], ah[mt][2], ah[mt][3], b0h, b1h);
                mma_tf32(acc[mt][t], ah[mt][0], ah[mt][1], ah[mt][2], ah[mt][3], b0l, b1l);
                mma_tf32(acc[mt][t], al[mt][0], al[mt][1], al[mt][2], al[mt][3], b0h, b1h);
            }
        }
    }
    __syncthreads();
}

// ============================================================
// Main fused kernel (tensor-core): 256 threads (8 warps), TBM=32
// (two m16 tiles per warp -> B cost amortized 2x).
//   stage1: h  = relu(edge @ M2 + cpre1)   [mma 3xTF32]
//   stage2: hp = relu(h @ W3 + c3)         [mma 3xTF32]
//   stage3: prob = sigmoid(hp . lpo_w + lpo_b)
// ============================================================
__global__ void __launch_bounds__(256) tgat_main(
    const float* __restrict__ edge,
    const float* __restrict__ lpo_w, const float* __restrict__ lpo_b,
    float* __restrict__ out, int B, int dup)
{
    __shared__ __align__(16) float sA[EMB * PA];    // [k][m=32] pitch 36, 36.9 KB
    __shared__ __align__(16) float sB[8 * PB];      // fp32 B chunk, 8.4 KB
    __shared__ float red[8 * TBM];                  // 1 KB

    const int tid  = threadIdx.x;
    const int lane = tid & 31;
    const int warp = tid >> 5;
    const int s    = lane & 3;
    const int q    = lane >> 2;
    const int b0   = blockIdx.x * TBM;

    // load edge [32][172] -> sA col-major [e][r]; zero-pad rows 172..175
    for (int i = tid; i < TBM * ED; i += 256) {
        int r = i / ED, e = i - r * ED;
        float v = (b0 + r < B) ? edge[b0 * ED + i] : 0.f;
        sA[e * PA + r] = v;
    }
    if (tid < 128) sA[(ED + (tid >> 5)) * PA + (tid & 31)] = 0.f;
    __syncthreads();

    float acc[2][4][4];
    #pragma unroll
    for (int mt = 0; mt < 2; mt++)
        #pragma unroll
        for (int t = 0; t < 4; t++)
            acc[mt][t][0] = acc[mt][t][1] = acc[mt][t][2] = acc[mt][t][3] = 0.f;

    // ---- stage 1: edge @ M2 (K = 176 padded, 22 chunks) ----
    mma_gemm_stage<K1P / 8>((const float4*)g_M2, ED, sA, sB, acc, lane, warp, tid);

    // ---- epilogue 1: h = relu(acc + cpre1) -> sA [col][row] ----
    #pragma unroll
    for (int mt = 0; mt < 2; mt++) {
        int mo = mt * 16;
        #pragma unroll
        for (int t = 0; t < 4; t++) {
            int col0 = warp * 32 + t * 8 + s * 2;
            float cp0 = g_cpre1[col0], cp1 = g_cpre1[col0 + 1];
            sA[col0 * PA + mo + q]           = fmaxf(acc[mt][t][0] + cp0, 0.f);
            sA[(col0 + 1) * PA + mo + q]     = fmaxf(acc[mt][t][1] + cp1, 0.f);
            sA[col0 * PA + mo + q + 8]       = fmaxf(acc[mt][t][2] + cp0, 0.f);
            sA[(col0 + 1) * PA + mo + q + 8] = fmaxf(acc[mt][t][3] + cp1, 0.f);
            acc[mt][t][0] = acc[mt][t][1] = acc[mt][t][2] = acc[mt][t][3] = 0.f;
        }
    }
    __syncthreads();

    // ---- stage 2: h @ W3 (K = 256, 32 chunks) ----
    mma_gemm_stage<EMB / 8>((const float4*)g_W3, EMB, sA, sB, acc, lane, warp, tid);

    // ---- epilogue 2: hp = relu(acc + c3); row-dots with lpo_w ----
    #pragma unroll
    for (int mt = 0; mt < 2; mt++) {
        float rs0 = 0.f, rs1 = 0.f;
        #pragma unroll
        for (int t = 0; t < 4; t++) {
            int col0 = warp * 32 + t * 8 + s * 2;
            float c30 = g_c3[col0], c31 = g_c3[col0 + 1];
            float w0 = lpo_w[col0], w1 = lpo_w[col0 + 1];
            rs0 += fmaxf(acc[mt][t][0] + c30, 0.f) * w0
                 + fmaxf(acc[mt][t][1] + c31, 0.f) * w1;
            rs1 += fmaxf(acc[mt][t][2] + c30, 0.f) * w0
                 + fmaxf(acc[mt][t][3] + c31, 0.f) * w1;
        }
        rs0 += __shfl_xor_sync(0xffffffffu, rs0, 1);
        rs0 += __shfl_xor_sync(0xffffffffu, rs0, 2);
        rs1 += __shfl_xor_sync(0xffffffffu, rs1, 1);
        rs1 += __shfl_xor_sync(0xffffffffu, rs1, 2);
        if (s == 0) {
            red[warp * TBM + mt * 16 + q]     = rs0;   // row mt*16 + q
            red[warp * TBM + mt * 16 + 8 + q] = rs1;   // row mt*16 + 8 + q
        }
    }
    __syncthreads();

    if (tid < TBM) {
        float sv = lpo_b[0];
        #pragma unroll
        for (int w2 = 0; w2 < 8; w2++) sv += red[w2 * TBM + tid];
        float prob = 1.f / (1.f + expf(-sv));
        int b = b0 + tid;
        if (b < B) {
            out[b] = prob;
            if (dup) out[B + b] = prob;
        }
    }
}

// ============================================================
// Launch. Input order (metadata):
//  0 src 1 dst 2 time 3 edge_feats 4 t2v_w 5 t2v_b
//  6 Wq 7 bq 8 Wk 9 bk 10 Wv 11 bv 12 Wo 13 bo
//  14 fc1_w 15 fc1_b 16 fc2_w 17 fc2_b
//  18 lp_src_w 19 lp_src_b 20 lp_dst_w 21 lp_dst_b 22 lp_out_w 23 lp_out_b
// ============================================================
extern "C" void kernel_launch(void* const* d_in, const int* in_sizes, int n_in,
                              void* d_out, int out_size)
{
    const float* edge  = (const float*)d_in[3];
    const float* t2v_b = (const float*)d_in[5];
    const float* Wv    = (const float*)d_in[10];
    const float* bv    = (const float*)d_in[11];
    const float* Wo    = (const float*)d_in[12];
    const float* bo    = (const float*)d_in[13];
    const float* fc1_w = (const float*)d_in[14];
    const float* fc1_b = (const float*)d_in[15];
    const float* fc2_w = (const float*)d_in[16];
    const float* fc2_b = (const float*)d_in[17];
    const float* lps_w = (const float*)d_in[18];
    const float* lps_b = (const float*)d_in[19];
    const float* lpd_w = (const float*)d_in[20];
    const float* lpd_b = (const float*)d_in[21];
    const float* lpo_w = (const float*)d_in[22];
    const float* lpo_b = (const float*)d_in[23];

    const int B = in_sizes[0];
    float* out = (float*)d_out;
    const int dup = (out_size >= 2 * B) ? 1 : 0;

    tgat_preP1<<<P1_GRID, 256>>>(Wv, bv, t2v_b, Wo, lps_w, lpd_w);
    tgat_preP2<<<P2_GRID, 256>>>(fc1_w, fc2_w, fc2_b, Wo, bo, lps_b, lpd_b);
    tgat_preP3<<<8, 256>>>(fc1_w, fc1_b);
    tgat_main<<<(B + TBM - 1) / TBM, 256>>>(edge, lpo_w, lpo_b, out, B, dup);
}